// round 15
// baseline (speedup 1.0000x reference)
#include <cuda_runtime.h>
#include <cuda_bf16.h>
#include <mma.h>
#include <cstdint>

using namespace nvcuda;

#define BS 8
#define C 512
#define NH 8
#define NB 512                        // batches per attention phase = BS*64
#define NX (BS*C*64*64)               // 16777216
#define NM (BS*64*64)                 // 32768
#define NBC64 ((size_t)NB * C * 64)   // 16777216
#define WCC (3*C*C)                   // elems per weight tensor (L,C,C)

// Scratch (no dynamic allocation allowed)
__device__ float g_xA[NX];                 // layout A: [bs][c][nr][nc] (exact fp32)
__device__ float g_xB[NX];                 // layout B: [bs][c][nc][nr] (exact fp32)
__device__ __nv_bfloat16 g_xAh[NX];        // bf16 copy of layout-A x (proj operand)
__device__ __nv_bfloat16 g_xBh[NX];        // bf16 copy of layout-B x
__device__ __nv_bfloat16 g_Wh[6 * WCC];    // bf16 weights (6 tensors)
__device__ float g_obuf[NBC64];            // attention output O[b][o][q] (fp32)
__device__ __nv_bfloat16 g_kqvh[3 * NBC64];// K,Q,V bf16 for one phase

__device__ __forceinline__ void st_bf4(__nv_bfloat16* p, float4 v) {
    __nv_bfloat162 a = __floats2bfloat162_rn(v.x, v.y);
    __nv_bfloat162 b = __floats2bfloat162_rn(v.z, v.w);
    uint2 u;
    u.x = *(uint32_t*)&a;
    u.y = *(uint32_t*)&b;
    *(uint2*)p = u;
}

// add fp32 bias to 8 packed bf16 (via fp32), repack
__device__ __forceinline__ uint4 addb8(uint4 u, float bias) {
    __nv_bfloat162* p = (__nv_bfloat162*)&u;
    uint4 r;
    __nv_bfloat162* q = (__nv_bfloat162*)&r;
    #pragma unroll
    for (int i = 0; i < 4; ++i) {
        float2 f = __bfloat1622float2(p[i]);
        q[i] = __floats2bfloat162_rn(f.x + bias, f.y + bias);
    }
    return r;
}

__device__ __forceinline__ void cp16(uint32_t saddr, const void* g) {
    asm volatile("cp.async.cg.shared.global [%0], [%1], 16;" :: "r"(saddr), "l"(g));
}
__device__ __forceinline__ void cp_commit() {
    asm volatile("cp.async.commit_group;");
}
template <int N>
__device__ __forceinline__ void cp_wait() {
    asm volatile("cp.async.wait_group %0;" :: "n"(N));
}

// ---------------------------------------------------------------------------
// Prepass: convert weights / x to bf16.
// ---------------------------------------------------------------------------
__global__ __launch_bounds__(256) void conv_w_kernel(
    const float* __restrict__ w0, const float* __restrict__ w1, const float* __restrict__ w2,
    const float* __restrict__ w3, const float* __restrict__ w4, const float* __restrict__ w5,
    __nv_bfloat16* __restrict__ out)
{
    int iv = blockIdx.x * 256 + threadIdx.x;       // vec4 index
    if (iv * 4 >= 6 * WCC) return;
    int i0 = iv * 4;
    int w = i0 / WCC, r = i0 - w * WCC;
    const float* src = (w == 0) ? w0 : (w == 1) ? w1 : (w == 2) ? w2
                     : (w == 3) ? w3 : (w == 4) ? w4 : w5;
    float4 v = *(const float4*)&src[r];
    st_bf4(&out[i0], v);
}

__global__ __launch_bounds__(256) void conv_x_kernel(
    const float* __restrict__ in, __nv_bfloat16* __restrict__ out)
{
    int i = blockIdx.x * 256 + threadIdx.x;
    float4 v = *(const float4*)&in[(size_t)i * 4];
    st_bf4(&out[(size_t)i * 4], v);
}

// ---------------------------------------------------------------------------
// Tensor-core projection (WMMA bf16 m16n16k16), 2-stage cp.async double
// buffer, 3 CTAs/SM (latency-bound -> more warps).
//   kqvh[p][b][o][n] = bf16( sum_c W_p[o][c] * X_b[c][n] )   (bias in attn)
// CTA: 128 o x 128 n (2 batches share W). 8 warps, warp tile 64m x 32n.
// Dynamic smem (bf16): 2 x (Ws[128][40] + Xs[32][136]) = 37888 B.
// ---------------------------------------------------------------------------
#define WS_ST 40
#define XS_ST 136
#define WS_STAGE (128 * WS_ST)
#define XS_STAGE (32 * XS_ST)
#define XS_BASE (2 * WS_STAGE)
#define NCHUNK 16
#define PSMEM ((2 * WS_STAGE + 2 * XS_STAGE) * 2)

__global__ __launch_bounds__(256, 3) void proj_tc_kernel(
    const __nv_bfloat16* __restrict__ xin,
    const __nv_bfloat16* __restrict__ Wk, const __nv_bfloat16* __restrict__ Wq,
    const __nv_bfloat16* __restrict__ Wv,
    __nv_bfloat16* __restrict__ kqvh)
{
    const int p = blockIdx.z;
    const __nv_bfloat16* __restrict__ W = (p == 0) ? Wk : ((p == 1) ? Wq : Wv);
    const int o0 = blockIdx.y << 7;
    const int b0 = blockIdx.x << 1;
    const int t  = threadIdx.x;
    const int w  = t >> 5, lane = t & 31;
    const int wm = w & 1, wn = w >> 1;     // warp tile: 64(m) x 32(n)

    const size_t base0 = (size_t)(b0 >> 6) * ((size_t)C * 4096) + (size_t)(b0 & 63) * 64;
    const size_t base1 = (size_t)((b0 + 1) >> 6) * ((size_t)C * 4096) + (size_t)((b0 + 1) & 63) * 64;

    extern __shared__ __nv_bfloat16 smh[];
    __shared__ float stage[8][16][16];
    uint32_t sbase;
    asm("{ .reg .u64 tmp; cvta.to.shared.u64 tmp, %1; cvt.u32.u64 %0, tmp; }"
        : "=r"(sbase) : "l"(smh));

    wmma::fragment<wmma::accumulator, 16, 16, 16, float> acc[4][2];
    #pragma unroll
    for (int mt = 0; mt < 4; ++mt)
        #pragma unroll
        for (int nt = 0; nt < 2; ++nt)
            wmma::fill_fragment(acc[mt][nt], 0.0f);

    auto load_stage = [&](int s, int kk) {
        uint32_t wbase = sbase + (uint32_t)(s * WS_STAGE) * 2u;
        #pragma unroll
        for (int r2 = 0; r2 < 2; ++r2) {
            int f = r2 * 256 + t;
            int o = f >> 2, c8 = (f & 3) << 3;
            cp16(wbase + (uint32_t)(o * WS_ST + c8) * 2u,
                 &W[(size_t)(o0 + o) * C + kk + c8]);
        }
        uint32_t xbase = sbase + (uint32_t)(XS_BASE + s * XS_STAGE) * 2u;
        #pragma unroll
        for (int r2 = 0; r2 < 2; ++r2) {
            int f = r2 * 256 + t;
            int k = f >> 4, n8 = (f & 15) << 3;
            size_t bb = (n8 < 64) ? base0 : base1;
            cp16(xbase + (uint32_t)(k * XS_ST + n8) * 2u,
                 &xin[bb + (size_t)(kk + k) * 4096 + (n8 & 63)]);
        }
        cp_commit();
    };

    load_stage(0, 0);
    int s = 0;
    for (int i = 0; i < NCHUNK; ++i) {
        if (i + 1 < NCHUNK) {
            load_stage(s ^ 1, (i + 1) * 32);
            cp_wait<1>();
        } else {
            cp_wait<0>();
        }
        __syncthreads();

        const __nv_bfloat16* Wsm = smh + s * WS_STAGE;
        const __nv_bfloat16* Xsm = smh + XS_BASE + s * XS_STAGE;
        #pragma unroll
        for (int ks = 0; ks < 2; ++ks) {
            wmma::fragment<wmma::matrix_a, 16, 16, 16, __nv_bfloat16, wmma::row_major> af[4];
            wmma::fragment<wmma::matrix_b, 16, 16, 16, __nv_bfloat16, wmma::row_major> bf[2];
            #pragma unroll
            for (int mt = 0; mt < 4; ++mt)
                wmma::load_matrix_sync(af[mt], &Wsm[((wm << 6) + (mt << 4)) * WS_ST + (ks << 4)], WS_ST);
            #pragma unroll
            for (int nt = 0; nt < 2; ++nt)
                wmma::load_matrix_sync(bf[nt], &Xsm[(ks << 4) * XS_ST + (wn << 5) + (nt << 4)], XS_ST);
            #pragma unroll
            for (int mt = 0; mt < 4; ++mt)
                #pragma unroll
                for (int nt = 0; nt < 2; ++nt)
                    wmma::mma_sync(acc[mt][nt], af[mt], bf[nt], acc[mt][nt]);
        }
        __syncthreads();
        s ^= 1;
    }

    // Epilogue: fp32 acc -> smem staging -> bf16 gmem
    float* st = &stage[w][0][0];
    const int row = lane >> 1, half = lane & 1;
    #pragma unroll
    for (int mt = 0; mt < 4; ++mt) {
        int mrow = o0 + (wm << 6) + (mt << 4);
        #pragma unroll
        for (int nt = 0; nt < 2; ++nt) {
            int n0 = (wn << 5) + (nt << 4);
            int bq_idx = b0 + (n0 >> 6);
            int nl0 = n0 & 63;
            wmma::store_matrix_sync(st, acc[mt][nt], 16, wmma::mem_row_major);
            __syncwarp();
            float4 v0 = *(float4*)&st[row * 16 + half * 8];
            float4 v1 = *(float4*)&st[row * 16 + half * 8 + 4];
            uint4 u;
            __nv_bfloat162 h0 = __floats2bfloat162_rn(v0.x, v0.y);
            __nv_bfloat162 h1 = __floats2bfloat162_rn(v0.z, v0.w);
            __nv_bfloat162 h2 = __floats2bfloat162_rn(v1.x, v1.y);
            __nv_bfloat162 h3 = __floats2bfloat162_rn(v1.z, v1.w);
            u.x = *(uint32_t*)&h0; u.y = *(uint32_t*)&h1;
            u.z = *(uint32_t*)&h2; u.w = *(uint32_t*)&h3;
            size_t g = ((size_t)(p * NB + bq_idx) * C + mrow + row) * 64 + nl0 + half * 8;
            *(uint4*)&kqvh[g] = u;
            __syncwarp();
        }
    }
}

// ---------------------------------------------------------------------------
// Tensor-core attention: one CTA per (batch, head).
// Wt (softmax weights) OVERLAYS Kh. smem 45056 B -> 5 CTA/SM.
// ---------------------------------------------------------------------------
#define AST 72   // bf16 row stride (elems)
#define SST 68   // fp32 row stride (elems)
#define ASMEM (3 * 64 * AST * 2 + 64 * SST * 4)   // K/Q/V bf16 + S fp32 = 45056

__global__ __launch_bounds__(256) void attn_kernel(
    const __nv_bfloat16* __restrict__ kqvh,
    float* __restrict__ obuf,
    const float* __restrict__ masks,
    const float* __restrict__ bkv, const float* __restrict__ bqv, const float* __restrict__ bvv,
    int maskT)
{
    const int b = blockIdx.x;
    const int h = blockIdx.y;
    const int t = threadIdx.x;

    extern __shared__ char smraw[];
    __nv_bfloat16* Kh = (__nv_bfloat16*)smraw;          // [64][AST]
    __nv_bfloat16* Qh = Kh + 64 * AST;
    __nv_bfloat16* Vh = Qh + 64 * AST;
    __nv_bfloat16* Wt = Kh;                             // OVERLAY: weights [k][q]
    float* S = (float*)(Vh + 64 * AST);                 // logits [k][q], [64][SST]
    __shared__ float Msm[64];

    const size_t kb = (size_t)b * (C * 64);
    const __nv_bfloat16* __restrict__ Kg = kqvh + kb;
    const __nv_bfloat16* __restrict__ Qg = kqvh + NBC64 + kb;
    const __nv_bfloat16* __restrict__ Vg = kqvh + 2 * NBC64 + kb;

    #pragma unroll
    for (int i = 0; i < 2; ++i) {
        int f = i * 256 + t;                 // 0..511
        int ch = f >> 3, c8 = (f & 7) << 3;  // 8-elem chunk
        int o = ch * NH + h;
        size_t g = (size_t)o * 64 + c8;
        float kbias = __ldg(&bkv[o]);
        float qbias = __ldg(&bqv[o]);
        float vbias = __ldg(&bvv[o]);
        *(uint4*)&Kh[ch * AST + c8] = addb8(*(const uint4*)&Kg[g], kbias);
        *(uint4*)&Qh[ch * AST + c8] = addb8(*(const uint4*)&Qg[g], qbias);
        *(uint4*)&Vh[ch * AST + c8] = addb8(*(const uint4*)&Vg[g], vbias);
    }
    const int bs = b >> 6, idx = b & 63;
    if (t < 64) {
        Msm[t] = maskT ? masks[bs * 4096 + t * 64 + idx]
                       : masks[bs * 4096 + idx * 64 + t];
    }
    __syncthreads();

    // ---- logits S[k][q] = sum_ch K[ch][k]*Q[ch][q]  (wmma, A=K col_major) ----
    const int w = t >> 5;
    const int mt = w & 3;              // k-tile (also ch-tile in AV)
    const int ntb = (w >> 2) << 1;     // first of 2 q-tiles
    {
        wmma::fragment<wmma::accumulator, 16, 16, 16, float> sacc[2];
        wmma::fill_fragment(sacc[0], 0.0f);
        wmma::fill_fragment(sacc[1], 0.0f);
        #pragma unroll
        for (int kc = 0; kc < 4; ++kc) {
            wmma::fragment<wmma::matrix_a, 16, 16, 16, __nv_bfloat16, wmma::col_major> a;
            wmma::load_matrix_sync(a, Kh + kc * 16 * AST + mt * 16, AST);
            #pragma unroll
            for (int j = 0; j < 2; ++j) {
                wmma::fragment<wmma::matrix_b, 16, 16, 16, __nv_bfloat16, wmma::row_major> bq;
                wmma::load_matrix_sync(bq, Qh + kc * 16 * AST + (ntb + j) * 16, AST);
                wmma::mma_sync(sacc[j], a, bq, sacc[j]);
            }
        }
        #pragma unroll
        for (int j = 0; j < 2; ++j)
            wmma::store_matrix_sync(&S[(mt * 16) * SST + (ntb + j) * 16], sacc[j],
                                    SST, wmma::mem_row_major);
    }
    __syncthreads();   // Kh last read above; Wt(=Kh) written below

    // ---- softmax over k (thread (kg,qg) owns 4x4 of S) ----
    const int kg = t & 15, qg = t >> 4;
    const int k0 = kg << 2, q0l = qg << 2;
    float acc[4][4];
    const float scale = 0.044194173824159216f;  // 1/sqrt(512)
    #pragma unroll
    for (int i = 0; i < 4; ++i) {
        float4 v = *(const float4*)&S[(k0 + i) * SST + q0l];
        float mpen = (1.0f - Msm[k0 + i]) * 1e8f;
        acc[i][0] = v.x * scale - mpen;
        acc[i][1] = v.y * scale - mpen;
        acc[i][2] = v.z * scale - mpen;
        acc[i][3] = v.w * scale - mpen;
    }
    #pragma unroll
    for (int j = 0; j < 4; ++j) {
        float mx = acc[0][j];
        #pragma unroll
        for (int i = 1; i < 4; ++i) mx = fmaxf(mx, acc[i][j]);
        #pragma unroll
        for (int off = 1; off < 16; off <<= 1)
            mx = fmaxf(mx, __shfl_xor_sync(0xffffffffu, mx, off));
        float s = 0.0f;
        float e[4];
        #pragma unroll
        for (int i = 0; i < 4; ++i) {
            e[i] = __expf(acc[i][j] - mx);
            s += e[i];
        }
        #pragma unroll
        for (int off = 1; off < 16; off <<= 1)
            s += __shfl_xor_sync(0xffffffffu, s, off);
        float inv = 1.0f / s;
        #pragma unroll
        for (int i = 0; i < 4; ++i) acc[i][j] = e[i] * inv;
    }
    // write weights (bf16) to Wt[k][q]  (overlays Kh)
    #pragma unroll
    for (int i = 0; i < 4; ++i) {
        __nv_bfloat162 w0 = __floats2bfloat162_rn(acc[i][0], acc[i][1]);
        __nv_bfloat162 w1 = __floats2bfloat162_rn(acc[i][2], acc[i][3]);
        uint2 u;
        u.x = *(uint32_t*)&w0;
        u.y = *(uint32_t*)&w1;
        *(uint2*)&Wt[(k0 + i) * AST + q0l] = u;
    }
    __syncthreads();

    // ---- O[ch][q] = sum_k V[ch][k] * Wt[k][q]  (wmma) -> obuf fp32 ----
    {
        wmma::fragment<wmma::accumulator, 16, 16, 16, float> oacc[2];
        wmma::fill_fragment(oacc[0], 0.0f);
        wmma::fill_fragment(oacc[1], 0.0f);
        #pragma unroll
        for (int kc = 0; kc < 4; ++kc) {
            wmma::fragment<wmma::matrix_a, 16, 16, 16, __nv_bfloat16, wmma::row_major> a;
            wmma::load_matrix_sync(a, Vh + (mt * 16) * AST + kc * 16, AST);
            #pragma unroll
            for (int j = 0; j < 2; ++j) {
                wmma::fragment<wmma::matrix_b, 16, 16, 16, __nv_bfloat16, wmma::row_major> bw;
                wmma::load_matrix_sync(bw, Wt + (kc * 16) * AST + (ntb + j) * 16, AST);
                wmma::mma_sync(oacc[j], a, bw, oacc[j]);
            }
        }
        float* ob = obuf + (size_t)b * (C * 64) + h * 64;
        #pragma unroll
        for (int j = 0; j < 2; ++j)
            wmma::store_matrix_sync(ob + (size_t)(mt * 16) * 512 + (ntb + j) * 16,
                                    oacc[j], 512, wmma::mem_row_major);
    }
}

// ---------------------------------------------------------------------------
// Fused transpose + residual: out[bs][c][j][i] = in[bs][c][i][j] + O[bs*64+i][c][j]
// Also writes a bf16 copy for the next projection.
// ---------------------------------------------------------------------------
__global__ __launch_bounds__(256) void addT_kernel(
    const float* __restrict__ in,
    const float* __restrict__ obuf,
    float* __restrict__ out,
    __nv_bfloat16* __restrict__ outH)
{
    const int bc = blockIdx.x;
    const int bs = bc >> 9, c = bc & 511;
    const int t = threadIdx.x;
    __shared__ float sm[64][65];

    const size_t inb = (size_t)bs * ((size_t)C * 4096) + (size_t)c * 4096;

    #pragma unroll
    for (int p = 0; p < 4; ++p) {
        int r = p * 16 + (t >> 4);
        int j4 = (t & 15) << 2;
        float4 xv = *(const float4*)&in[inb + (size_t)r * 64 + j4];
        float4 ov = *(const float4*)&obuf[((size_t)(bs * 64 + r) * C + c) * 64 + j4];
        sm[r][j4 + 0] = xv.x + ov.x;
        sm[r][j4 + 1] = xv.y + ov.y;
        sm[r][j4 + 2] = xv.z + ov.z;
        sm[r][j4 + 3] = xv.w + ov.w;
    }
    __syncthreads();
    #pragma unroll
    for (int p = 0; p < 4; ++p) {
        int j = p * 16 + (t >> 4);
        int i4 = (t & 15) << 2;
        float4 val = make_float4(sm[i4 + 0][j], sm[i4 + 1][j],
                                 sm[i4 + 2][j], sm[i4 + 3][j]);
        *(float4*)&out[inb + (size_t)j * 64 + i4] = val;
        st_bf4(&outH[inb + (size_t)j * 64 + i4], val);
    }
}

__global__ void copy_masks_kernel(const float* __restrict__ m, float* __restrict__ o)
{
    int i = blockIdx.x * 256 + threadIdx.x;
    if (i < NM) o[i] = m[i];
}

// ---------------------------------------------------------------------------
extern "C" void kernel_launch(void* const* d_in, const int* in_sizes, int n_in,
                              void* d_out, int out_size)
{
    const float* x     = (const float*)d_in[0];
    const float* masks = (const float*)d_in[1];

    const float* W[6];
    const float* B[6];
    if (n_in >= 14 && in_sizes[3] == 3 * C) {
        const int wi[6] = {2, 4, 6, 8, 10, 12};
        const int bi[6] = {3, 5, 7, 9, 11, 13};
        for (int i = 0; i < 6; ++i) {
            W[i] = (const float*)d_in[wi[i]];
            B[i] = (const float*)d_in[bi[i]];
        }
    } else {
        for (int i = 0; i < 6; ++i) {
            W[i] = (const float*)d_in[2 + i];
            B[i] = (const float*)d_in[8 + i];
        }
    }

    float *xA, *xB, *obuf;
    __nv_bfloat16 *xAh, *xBh, *Wh, *kqvh;
    cudaGetSymbolAddress((void**)&xA,   g_xA);
    cudaGetSymbolAddress((void**)&xB,   g_xB);
    cudaGetSymbolAddress((void**)&xAh,  g_xAh);
    cudaGetSymbolAddress((void**)&xBh,  g_xBh);
    cudaGetSymbolAddress((void**)&Wh,   g_Wh);
    cudaGetSymbolAddress((void**)&obuf, g_obuf);
    cudaGetSymbolAddress((void**)&kqvh, g_kqvh);

    cudaFuncSetAttribute(attn_kernel, cudaFuncAttributeMaxDynamicSharedMemorySize, ASMEM);
    cudaFuncSetAttribute(proj_tc_kernel, cudaFuncAttributeMaxDynamicSharedMemorySize, PSMEM);

    // Prepass: bf16 conversion of weights and layer-0 x
    conv_w_kernel<<<(6 * WCC / 4 + 255) / 256, 256>>>(
        W[0], W[1], W[2], W[3], W[4], W[5], Wh);
    conv_x_kernel<<<NX / 1024, 256>>>(x, xAh);

    float* xo = (float*)d_out;
    const float* xin = x;                       // exact fp32 x for residual
    const __nv_bfloat16* xinh = xAh;            // bf16 x for proj
    for (int l = 0; l < 3; ++l) {
        size_t wo = (size_t)l * C * C;
        size_t bo = (size_t)l * C;
        // column attention (layout A in, layout B out)
        proj_tc_kernel<<<dim3(NB / 2, 4, 3), 256, PSMEM>>>(
            xinh, Wh + 0 * WCC + wo, Wh + 1 * WCC + wo, Wh + 2 * WCC + wo, kqvh);
        attn_kernel<<<dim3(NB, NH), 256, ASMEM>>>(
            kqvh, obuf, masks, B[0] + bo, B[1] + bo, B[2] + bo, 0);
        addT_kernel<<<BS * C, 256>>>(xin, obuf, xB, xBh);
        // row attention (layout B in, layout A out)
        proj_tc_kernel<<<dim3(NB / 2, 4, 3), 256, PSMEM>>>(
            xBh, Wh + 3 * WCC + wo, Wh + 4 * WCC + wo, Wh + 5 * WCC + wo, kqvh);
        attn_kernel<<<dim3(NB, NH), 256, ASMEM>>>(
            kqvh, obuf, masks, B[3] + bo, B[4] + bo, B[5] + bo, 1);
        float* xout = (l == 2) ? xo : xA;
        addT_kernel<<<BS * C, 256>>>(xB, obuf, xout, xAh);
        xin = xA;
        xinh = xAh;
    }

    if (out_size >= NX + NM) {
        copy_masks_kernel<<<(NM + 255) / 256, 256>>>(masks, xo + NX);
    }
}

// round 16
// speedup vs baseline: 1.6985x; 1.6985x over previous
#include <cuda_runtime.h>
#include <cuda_bf16.h>
#include <mma.h>
#include <cstdint>

using namespace nvcuda;

#define BS 8
#define C 512
#define NH 8
#define NB 512                        // batches per attention phase = BS*64
#define NX (BS*C*64*64)               // 16777216
#define NM (BS*64*64)                 // 32768
#define NBC64 ((size_t)NB * C * 64)   // 16777216
#define WCC (3*C*C)                   // elems per weight tensor (L,C,C)

// Scratch (no dynamic allocation allowed)
__device__ float g_xA[NX];                 // layout A: [bs][c][nr][nc] (exact fp32)
__device__ float g_xB[NX];                 // layout B: [bs][c][nc][nr] (exact fp32)
__device__ __nv_bfloat16 g_xAh[NX];        // bf16 copy of layout-A x (proj operand)
__device__ __nv_bfloat16 g_xBh[NX];        // bf16 copy of layout-B x
__device__ __nv_bfloat16 g_Wh[6 * WCC];    // bf16 weights (6 tensors)
__device__ float g_obuf[NBC64];            // attention output O[b][o][q] (fp32)
__device__ __nv_bfloat16 g_kqvh[3 * NBC64];// K,Q,V bf16 for one phase

__device__ __forceinline__ void st_bf4(__nv_bfloat16* p, float4 v) {
    __nv_bfloat162 a = __floats2bfloat162_rn(v.x, v.y);
    __nv_bfloat162 b = __floats2bfloat162_rn(v.z, v.w);
    uint2 u;
    u.x = *(uint32_t*)&a;
    u.y = *(uint32_t*)&b;
    *(uint2*)p = u;
}

// add fp32 bias to 8 packed bf16 (via fp32), repack
__device__ __forceinline__ uint4 addb8(uint4 u, float bias) {
    __nv_bfloat162* p = (__nv_bfloat162*)&u;
    uint4 r;
    __nv_bfloat162* q = (__nv_bfloat162*)&r;
    #pragma unroll
    for (int i = 0; i < 4; ++i) {
        float2 f = __bfloat1622float2(p[i]);
        q[i] = __floats2bfloat162_rn(f.x + bias, f.y + bias);
    }
    return r;
}

__device__ __forceinline__ void cp16(uint32_t saddr, const void* g) {
    asm volatile("cp.async.cg.shared.global [%0], [%1], 16;" :: "r"(saddr), "l"(g));
}
__device__ __forceinline__ void cp_commit() {
    asm volatile("cp.async.commit_group;");
}
template <int N>
__device__ __forceinline__ void cp_wait() {
    asm volatile("cp.async.wait_group %0;" :: "n"(N));
}

// ---------------------------------------------------------------------------
// Prepass: convert weights / x to bf16.
// ---------------------------------------------------------------------------
__global__ __launch_bounds__(256) void conv_w_kernel(
    const float* __restrict__ w0, const float* __restrict__ w1, const float* __restrict__ w2,
    const float* __restrict__ w3, const float* __restrict__ w4, const float* __restrict__ w5,
    __nv_bfloat16* __restrict__ out)
{
    int iv = blockIdx.x * 256 + threadIdx.x;       // vec4 index
    if (iv * 4 >= 6 * WCC) return;
    int i0 = iv * 4;
    int w = i0 / WCC, r = i0 - w * WCC;
    const float* src = (w == 0) ? w0 : (w == 1) ? w1 : (w == 2) ? w2
                     : (w == 3) ? w3 : (w == 4) ? w4 : w5;
    float4 v = *(const float4*)&src[r];
    st_bf4(&out[i0], v);
}

__global__ __launch_bounds__(256) void conv_x_kernel(
    const float* __restrict__ in, __nv_bfloat16* __restrict__ out)
{
    int i = blockIdx.x * 256 + threadIdx.x;
    float4 v = *(const float4*)&in[(size_t)i * 4];
    st_bf4(&out[(size_t)i * 4], v);
}

// ---------------------------------------------------------------------------
// Tensor-core projection (WMMA bf16 m16n16k16), 3-stage cp.async pipeline,
// ONE __syncthreads per k-chunk.  (R14 configuration — best measured.)
//   kqvh[p][b][o][n] = bf16( sum_c W_p[o][c] * X_b[c][n] )   (bias in attn)
// CTA: 128 o x 128 n (2 batches share W). 8 warps, warp tile 64m x 32n.
// Dynamic smem (bf16): 3 x (Ws[128][40] + Xs[32][136]) = 56832 B.
// ---------------------------------------------------------------------------
#define WS_ST 40
#define XS_ST 136
#define WS_STAGE (128 * WS_ST)
#define XS_STAGE (32 * XS_ST)
#define XS_BASE (3 * WS_STAGE)
#define NCHUNK 16
#define PSMEM ((3 * WS_STAGE + 3 * XS_STAGE) * 2)

__global__ __launch_bounds__(256, 2) void proj_tc_kernel(
    const __nv_bfloat16* __restrict__ xin,
    const __nv_bfloat16* __restrict__ Wk, const __nv_bfloat16* __restrict__ Wq,
    const __nv_bfloat16* __restrict__ Wv,
    __nv_bfloat16* __restrict__ kqvh)
{
    const int p = blockIdx.z;
    const __nv_bfloat16* __restrict__ W = (p == 0) ? Wk : ((p == 1) ? Wq : Wv);
    const int o0 = blockIdx.y << 7;
    const int b0 = blockIdx.x << 1;
    const int t  = threadIdx.x;
    const int w  = t >> 5, lane = t & 31;
    const int wm = w & 1, wn = w >> 1;     // warp tile: 64(m) x 32(n)

    const size_t base0 = (size_t)(b0 >> 6) * ((size_t)C * 4096) + (size_t)(b0 & 63) * 64;
    const size_t base1 = (size_t)((b0 + 1) >> 6) * ((size_t)C * 4096) + (size_t)((b0 + 1) & 63) * 64;

    extern __shared__ __nv_bfloat16 smh[];
    __shared__ float stage[8][16][16];
    uint32_t sbase;
    asm("{ .reg .u64 tmp; cvta.to.shared.u64 tmp, %1; cvt.u32.u64 %0, tmp; }"
        : "=r"(sbase) : "l"(smh));

    wmma::fragment<wmma::accumulator, 16, 16, 16, float> acc[4][2];
    #pragma unroll
    for (int mt = 0; mt < 4; ++mt)
        #pragma unroll
        for (int nt = 0; nt < 2; ++nt)
            wmma::fill_fragment(acc[mt][nt], 0.0f);

    auto load_stage = [&](int s, int kk) {
        uint32_t wbase = sbase + (uint32_t)(s * WS_STAGE) * 2u;
        #pragma unroll
        for (int r2 = 0; r2 < 2; ++r2) {
            int f = r2 * 256 + t;
            int o = f >> 2, c8 = (f & 3) << 3;
            cp16(wbase + (uint32_t)(o * WS_ST + c8) * 2u,
                 &W[(size_t)(o0 + o) * C + kk + c8]);
        }
        uint32_t xbase = sbase + (uint32_t)(XS_BASE + s * XS_STAGE) * 2u;
        #pragma unroll
        for (int r2 = 0; r2 < 2; ++r2) {
            int f = r2 * 256 + t;
            int k = f >> 4, n8 = (f & 15) << 3;
            size_t bb = (n8 < 64) ? base0 : base1;
            cp16(xbase + (uint32_t)(k * XS_ST + n8) * 2u,
                 &xin[bb + (size_t)(kk + k) * 4096 + (n8 & 63)]);
        }
        cp_commit();
    };

    // prologue: stages 0,1 in flight
    load_stage(0, 0);
    load_stage(1, 32);

    for (int i = 0; i < NCHUNK; ++i) {
        const int s = i % 3;
        if (i < NCHUNK - 1) { cp_wait<1>(); } else { cp_wait<0>(); }
        __syncthreads();
        if (i + 2 < NCHUNK) load_stage((i + 2) % 3, (i + 2) * 32);

        const __nv_bfloat16* Wsm = smh + s * WS_STAGE;
        const __nv_bfloat16* Xsm = smh + XS_BASE + s * XS_STAGE;
        #pragma unroll
        for (int ks = 0; ks < 2; ++ks) {
            wmma::fragment<wmma::matrix_a, 16, 16, 16, __nv_bfloat16, wmma::row_major> af[4];
            wmma::fragment<wmma::matrix_b, 16, 16, 16, __nv_bfloat16, wmma::row_major> bf[2];
            #pragma unroll
            for (int mt = 0; mt < 4; ++mt)
                wmma::load_matrix_sync(af[mt], &Wsm[((wm << 6) + (mt << 4)) * WS_ST + (ks << 4)], WS_ST);
            #pragma unroll
            for (int nt = 0; nt < 2; ++nt)
                wmma::load_matrix_sync(bf[nt], &Xsm[(ks << 4) * XS_ST + (wn << 5) + (nt << 4)], XS_ST);
            #pragma unroll
            for (int mt = 0; mt < 4; ++mt)
                #pragma unroll
                for (int nt = 0; nt < 2; ++nt)
                    wmma::mma_sync(acc[mt][nt], af[mt], bf[nt], acc[mt][nt]);
        }
    }
    __syncthreads();

    // Epilogue: fp32 acc -> smem staging -> bf16 gmem
    float* st = &stage[w][0][0];
    const int row = lane >> 1, half = lane & 1;
    #pragma unroll
    for (int mt = 0; mt < 4; ++mt) {
        int mrow = o0 + (wm << 6) + (mt << 4);
        #pragma unroll
        for (int nt = 0; nt < 2; ++nt) {
            int n0 = (wn << 5) + (nt << 4);
            int bq_idx = b0 + (n0 >> 6);
            int nl0 = n0 & 63;
            wmma::store_matrix_sync(st, acc[mt][nt], 16, wmma::mem_row_major);
            __syncwarp();
            float4 v0 = *(float4*)&st[row * 16 + half * 8];
            float4 v1 = *(float4*)&st[row * 16 + half * 8 + 4];
            uint4 u;
            __nv_bfloat162 h0 = __floats2bfloat162_rn(v0.x, v0.y);
            __nv_bfloat162 h1 = __floats2bfloat162_rn(v0.z, v0.w);
            __nv_bfloat162 h2 = __floats2bfloat162_rn(v1.x, v1.y);
            __nv_bfloat162 h3 = __floats2bfloat162_rn(v1.z, v1.w);
            u.x = *(uint32_t*)&h0; u.y = *(uint32_t*)&h1;
            u.z = *(uint32_t*)&h2; u.w = *(uint32_t*)&h3;
            size_t g = ((size_t)(p * NB + bq_idx) * C + mrow + row) * 64 + nl0 + half * 8;
            *(uint4*)&kqvh[g] = u;
            __syncwarp();
        }
    }
}

// ---------------------------------------------------------------------------
// Tensor-core attention: one CTA per (batch, head).
// Wt (softmax weights) OVERLAYS Kh — Kh is dead after the logits phase and
// the existing barriers separate all reads/writes. smem 45056 B -> 5 CTA/SM.
// ---------------------------------------------------------------------------
#define AST 72   // bf16 row stride (elems)
#define SST 68   // fp32 row stride (elems)
#define ASMEM (3 * 64 * AST * 2 + 64 * SST * 4)   // K/Q/V bf16 + S fp32 = 45056

__global__ __launch_bounds__(256) void attn_kernel(
    const __nv_bfloat16* __restrict__ kqvh,
    float* __restrict__ obuf,
    const float* __restrict__ masks,
    const float* __restrict__ bkv, const float* __restrict__ bqv, const float* __restrict__ bvv,
    int maskT)
{
    const int b = blockIdx.x;
    const int h = blockIdx.y;
    const int t = threadIdx.x;

    extern __shared__ char smraw[];
    __nv_bfloat16* Kh = (__nv_bfloat16*)smraw;          // [64][AST]
    __nv_bfloat16* Qh = Kh + 64 * AST;
    __nv_bfloat16* Vh = Qh + 64 * AST;
    __nv_bfloat16* Wt = Kh;                             // OVERLAY: weights [k][q]
    float* S = (float*)(Vh + 64 * AST);                 // logits [k][q], [64][SST]
    __shared__ float Msm[64];

    const size_t kb = (size_t)b * (C * 64);
    const __nv_bfloat16* __restrict__ Kg = kqvh + kb;
    const __nv_bfloat16* __restrict__ Qg = kqvh + NBC64 + kb;
    const __nv_bfloat16* __restrict__ Vg = kqvh + 2 * NBC64 + kb;

    #pragma unroll
    for (int i = 0; i < 2; ++i) {
        int f = i * 256 + t;                 // 0..511
        int ch = f >> 3, c8 = (f & 7) << 3;  // 8-elem chunk
        int o = ch * NH + h;
        size_t g = (size_t)o * 64 + c8;
        float kbias = __ldg(&bkv[o]);
        float qbias = __ldg(&bqv[o]);
        float vbias = __ldg(&bvv[o]);
        *(uint4*)&Kh[ch * AST + c8] = addb8(*(const uint4*)&Kg[g], kbias);
        *(uint4*)&Qh[ch * AST + c8] = addb8(*(const uint4*)&Qg[g], qbias);
        *(uint4*)&Vh[ch * AST + c8] = addb8(*(const uint4*)&Vg[g], vbias);
    }
    const int bs = b >> 6, idx = b & 63;
    if (t < 64) {
        Msm[t] = maskT ? masks[bs * 4096 + t * 64 + idx]
                       : masks[bs * 4096 + idx * 64 + t];
    }
    __syncthreads();

    // ---- logits S[k][q] = sum_ch K[ch][k]*Q[ch][q]  (wmma, A=K col_major) ----
    const int w = t >> 5;
    const int mt = w & 3;              // k-tile (also ch-tile in AV)
    const int ntb = (w >> 2) << 1;     // first of 2 q-tiles
    {
        wmma::fragment<wmma::accumulator, 16, 16, 16, float> sacc[2];
        wmma::fill_fragment(sacc[0], 0.0f);
        wmma::fill_fragment(sacc[1], 0.0f);
        #pragma unroll
        for (int kc = 0; kc < 4; ++kc) {
            wmma::fragment<wmma::matrix_a, 16, 16, 16, __nv_bfloat16, wmma::col_major> a;
            wmma::load_matrix_sync(a, Kh + kc * 16 * AST + mt * 16, AST);
            #pragma unroll
            for (int j = 0; j < 2; ++j) {
                wmma::fragment<wmma::matrix_b, 16, 16, 16, __nv_bfloat16, wmma::row_major> bq;
                wmma::load_matrix_sync(bq, Qh + kc * 16 * AST + (ntb + j) * 16, AST);
                wmma::mma_sync(sacc[j], a, bq, sacc[j]);
            }
        }
        #pragma unroll
        for (int j = 0; j < 2; ++j)
            wmma::store_matrix_sync(&S[(mt * 16) * SST + (ntb + j) * 16], sacc[j],
                                    SST, wmma::mem_row_major);
    }
    __syncthreads();   // Kh last read above; Wt(=Kh) written below

    // ---- softmax over k (thread (kg,qg) owns 4x4 of S) ----
    const int kg = t & 15, qg = t >> 4;
    const int k0 = kg << 2, q0l = qg << 2;
    float acc[4][4];
    const float scale = 0.044194173824159216f;  // 1/sqrt(512)
    #pragma unroll
    for (int i = 0; i < 4; ++i) {
        float4 v = *(const float4*)&S[(k0 + i) * SST + q0l];
        float mpen = (1.0f - Msm[k0 + i]) * 1e8f;
        acc[i][0] = v.x * scale - mpen;
        acc[i][1] = v.y * scale - mpen;
        acc[i][2] = v.z * scale - mpen;
        acc[i][3] = v.w * scale - mpen;
    }
    #pragma unroll
    for (int j = 0; j < 4; ++j) {
        float mx = acc[0][j];
        #pragma unroll
        for (int i = 1; i < 4; ++i) mx = fmaxf(mx, acc[i][j]);
        #pragma unroll
        for (int off = 1; off < 16; off <<= 1)
            mx = fmaxf(mx, __shfl_xor_sync(0xffffffffu, mx, off));
        float s = 0.0f;
        float e[4];
        #pragma unroll
        for (int i = 0; i < 4; ++i) {
            e[i] = __expf(acc[i][j] - mx);
            s += e[i];
        }
        #pragma unroll
        for (int off = 1; off < 16; off <<= 1)
            s += __shfl_xor_sync(0xffffffffu, s, off);
        float inv = 1.0f / s;
        #pragma unroll
        for (int i = 0; i < 4; ++i) acc[i][j] = e[i] * inv;
    }
    // write weights (bf16) to Wt[k][q]  (overlays Kh)
    #pragma unroll
    for (int i = 0; i < 4; ++i) {
        __nv_bfloat162 w0 = __floats2bfloat162_rn(acc[i][0], acc[i][1]);
        __nv_bfloat162 w1 = __floats2bfloat162_rn(acc[i][2], acc[i][3]);
        uint2 u;
        u.x = *(uint32_t*)&w0;
        u.y = *(uint32_t*)&w1;
        *(uint2*)&Wt[(k0 + i) * AST + q0l] = u;
    }
    __syncthreads();

    // ---- O[ch][q] = sum_k V[ch][k] * Wt[k][q]  (wmma) -> obuf fp32 ----
    {
        wmma::fragment<wmma::accumulator, 16, 16, 16, float> oacc[2];
        wmma::fill_fragment(oacc[0], 0.0f);
        wmma::fill_fragment(oacc[1], 0.0f);
        #pragma unroll
        for (int kc = 0; kc < 4; ++kc) {
            wmma::fragment<wmma::matrix_a, 16, 16, 16, __nv_bfloat16, wmma::row_major> a;
            wmma::load_matrix_sync(a, Vh + (mt * 16) * AST + kc * 16, AST);
            #pragma unroll
            for (int j = 0; j < 2; ++j) {
                wmma::fragment<wmma::matrix_b, 16, 16, 16, __nv_bfloat16, wmma::row_major> bw;
                wmma::load_matrix_sync(bw, Wt + (kc * 16) * AST + (ntb + j) * 16, AST);
                wmma::mma_sync(oacc[j], a, bw, oacc[j]);
            }
        }
        float* ob = obuf + (size_t)b * (C * 64) + h * 64;
        #pragma unroll
        for (int j = 0; j < 2; ++j)
            wmma::store_matrix_sync(ob + (size_t)(mt * 16) * 512 + (ntb + j) * 16,
                                    oacc[j], 512, wmma::mem_row_major);
    }
}

// ---------------------------------------------------------------------------
// Fused transpose + residual: out[bs][c][j][i] = in[bs][c][i][j] + O[bs*64+i][c][j]
// Also writes a bf16 copy for the next projection.
// ---------------------------------------------------------------------------
__global__ __launch_bounds__(256) void addT_kernel(
    const float* __restrict__ in,
    const float* __restrict__ obuf,
    float* __restrict__ out,
    __nv_bfloat16* __restrict__ outH)
{
    const int bc = blockIdx.x;
    const int bs = bc >> 9, c = bc & 511;
    const int t = threadIdx.x;
    __shared__ float sm[64][65];

    const size_t inb = (size_t)bs * ((size_t)C * 4096) + (size_t)c * 4096;

    #pragma unroll
    for (int p = 0; p < 4; ++p) {
        int r = p * 16 + (t >> 4);
        int j4 = (t & 15) << 2;
        float4 xv = *(const float4*)&in[inb + (size_t)r * 64 + j4];
        float4 ov = *(const float4*)&obuf[((size_t)(bs * 64 + r) * C + c) * 64 + j4];
        sm[r][j4 + 0] = xv.x + ov.x;
        sm[r][j4 + 1] = xv.y + ov.y;
        sm[r][j4 + 2] = xv.z + ov.z;
        sm[r][j4 + 3] = xv.w + ov.w;
    }
    __syncthreads();
    #pragma unroll
    for (int p = 0; p < 4; ++p) {
        int j = p * 16 + (t >> 4);
        int i4 = (t & 15) << 2;
        float4 val = make_float4(sm[i4 + 0][j], sm[i4 + 1][j],
                                 sm[i4 + 2][j], sm[i4 + 3][j]);
        *(float4*)&out[inb + (size_t)j * 64 + i4] = val;
        st_bf4(&outH[inb + (size_t)j * 64 + i4], val);
    }
}

__global__ void copy_masks_kernel(const float* __restrict__ m, float* __restrict__ o)
{
    int i = blockIdx.x * 256 + threadIdx.x;
    if (i < NM) o[i] = m[i];
}

// ---------------------------------------------------------------------------
extern "C" void kernel_launch(void* const* d_in, const int* in_sizes, int n_in,
                              void* d_out, int out_size)
{
    const float* x     = (const float*)d_in[0];
    const float* masks = (const float*)d_in[1];

    const float* W[6];
    const float* B[6];
    if (n_in >= 14 && in_sizes[3] == 3 * C) {
        const int wi[6] = {2, 4, 6, 8, 10, 12};
        const int bi[6] = {3, 5, 7, 9, 11, 13};
        for (int i = 0; i < 6; ++i) {
            W[i] = (const float*)d_in[wi[i]];
            B[i] = (const float*)d_in[bi[i]];
        }
    } else {
        for (int i = 0; i < 6; ++i) {
            W[i] = (const float*)d_in[2 + i];
            B[i] = (const float*)d_in[8 + i];
        }
    }

    float *xA, *xB, *obuf;
    __nv_bfloat16 *xAh, *xBh, *Wh, *kqvh;
    cudaGetSymbolAddress((void**)&xA,   g_xA);
    cudaGetSymbolAddress((void**)&xB,   g_xB);
    cudaGetSymbolAddress((void**)&xAh,  g_xAh);
    cudaGetSymbolAddress((void**)&xBh,  g_xBh);
    cudaGetSymbolAddress((void**)&Wh,   g_Wh);
    cudaGetSymbolAddress((void**)&obuf, g_obuf);
    cudaGetSymbolAddress((void**)&kqvh, g_kqvh);

    cudaFuncSetAttribute(attn_kernel, cudaFuncAttributeMaxDynamicSharedMemorySize, ASMEM);
    cudaFuncSetAttribute(proj_tc_kernel, cudaFuncAttributeMaxDynamicSharedMemorySize, PSMEM);

    // Prepass: bf16 conversion of weights and layer-0 x
    conv_w_kernel<<<(6 * WCC / 4 + 255) / 256, 256>>>(
        W[0], W[1], W[2], W[3], W[4], W[5], Wh);
    conv_x_kernel<<<NX / 1024, 256>>>(x, xAh);

    float* xo = (float*)d_out;
    const float* xin = x;                       // exact fp32 x for residual
    const __nv_bfloat16* xinh = xAh;            // bf16 x for proj
    for (int l = 0; l < 3; ++l) {
        size_t wo = (size_t)l * C * C;
        size_t bo = (size_t)l * C;
        // column attention (layout A in, layout B out)
        proj_tc_kernel<<<dim3(NB / 2, 4, 3), 256, PSMEM>>>(
            xinh, Wh + 0 * WCC + wo, Wh + 1 * WCC + wo, Wh + 2 * WCC + wo, kqvh);
        attn_kernel<<<dim3(NB, NH), 256, ASMEM>>>(
            kqvh, obuf, masks, B[0] + bo, B[1] + bo, B[2] + bo, 0);
        addT_kernel<<<BS * C, 256>>>(xin, obuf, xB, xBh);
        // row attention (layout B in, layout A out)
        proj_tc_kernel<<<dim3(NB / 2, 4, 3), 256, PSMEM>>>(
            xBh, Wh + 3 * WCC + wo, Wh + 4 * WCC + wo, Wh + 5 * WCC + wo, kqvh);
        attn_kernel<<<dim3(NB, NH), 256, ASMEM>>>(
            kqvh, obuf, masks, B[3] + bo, B[4] + bo, B[5] + bo, 1);
        float* xout = (l == 2) ? xo : xA;
        addT_kernel<<<BS * C, 256>>>(xB, obuf, xout, xAh);
        xin = xA;
        xinh = xAh;
    }

    if (out_size >= NX + NM) {
        copy_masks_kernel<<<(NM + 255) / 256, 256>>>(masks, xo + NX);
    }
}

// round 17
// speedup vs baseline: 1.7302x; 1.0187x over previous
#include <cuda_runtime.h>
#include <cuda_bf16.h>
#include <mma.h>
#include <cstdint>

using namespace nvcuda;

#define BS 8
#define C 512
#define NH 8
#define NB 512                        // batches per attention phase = BS*64
#define NX (BS*C*64*64)               // 16777216
#define NM (BS*64*64)                 // 32768
#define NBC64 ((size_t)NB * C * 64)   // 16777216
#define WCC (3*C*C)                   // elems per weight tensor (L,C,C)

// Scratch (no dynamic allocation allowed)
__device__ float g_xA[NX];                 // layout A: [bs][c][nr][nc] (exact fp32)
__device__ float g_xB[NX];                 // layout B: [bs][c][nc][nr] (exact fp32)
__device__ __nv_bfloat16 g_xAh[NX];        // bf16 copy of layout-A x (proj operand)
__device__ __nv_bfloat16 g_xBh[NX];        // bf16 copy of layout-B x
__device__ __nv_bfloat16 g_Wh[6 * WCC];    // bf16 weights (6 tensors)
__device__ float g_obuf[NBC64];            // attention output O[b][o][q] (fp32)
__device__ __nv_bfloat16 g_kqvh[3 * NBC64];// K,Q,V bf16 (bias included) for one phase

__device__ __forceinline__ void st_bf4(__nv_bfloat16* p, float4 v) {
    __nv_bfloat162 a = __floats2bfloat162_rn(v.x, v.y);
    __nv_bfloat162 b = __floats2bfloat162_rn(v.z, v.w);
    uint2 u;
    u.x = *(uint32_t*)&a;
    u.y = *(uint32_t*)&b;
    *(uint2*)p = u;
}

__device__ __forceinline__ void cp16(uint32_t saddr, const void* g) {
    asm volatile("cp.async.cg.shared.global [%0], [%1], 16;" :: "r"(saddr), "l"(g));
}
__device__ __forceinline__ void cp_commit() {
    asm volatile("cp.async.commit_group;");
}
template <int N>
__device__ __forceinline__ void cp_wait() {
    asm volatile("cp.async.wait_group %0;" :: "n"(N));
}
__device__ __forceinline__ uint32_t smem_u32(const void* p) {
    uint32_t a;
    asm("{ .reg .u64 t; cvta.to.shared.u64 t, %1; cvt.u32.u64 %0, t; }" : "=r"(a) : "l"(p));
    return a;
}

// ---------------------------------------------------------------------------
// Prepass: convert weights / x to bf16.
// ---------------------------------------------------------------------------
__global__ __launch_bounds__(256) void conv_w_kernel(
    const float* __restrict__ w0, const float* __restrict__ w1, const float* __restrict__ w2,
    const float* __restrict__ w3, const float* __restrict__ w4, const float* __restrict__ w5,
    __nv_bfloat16* __restrict__ out)
{
    int iv = blockIdx.x * 256 + threadIdx.x;       // vec4 index
    if (iv * 4 >= 6 * WCC) return;
    int i0 = iv * 4;
    int w = i0 / WCC, r = i0 - w * WCC;
    const float* src = (w == 0) ? w0 : (w == 1) ? w1 : (w == 2) ? w2
                     : (w == 3) ? w3 : (w == 4) ? w4 : w5;
    float4 v = *(const float4*)&src[r];
    st_bf4(&out[i0], v);
}

__global__ __launch_bounds__(256) void conv_x_kernel(
    const float* __restrict__ in, __nv_bfloat16* __restrict__ out)
{
    int i = blockIdx.x * 256 + threadIdx.x;
    float4 v = *(const float4*)&in[(size_t)i * 4];
    st_bf4(&out[(size_t)i * 4], v);
}

// ---------------------------------------------------------------------------
// Tensor-core projection (WMMA bf16 m16n16k16), 3-stage cp.async pipeline.
//   kqvh[p][b][o][n] = bf16( sum_c W_p[o][c] * X_b[c][n] + bias_p[o] )
// CTA: 128 o x 128 n (2 batches share W). 8 warps, warp tile 64m x 32n.
// Dynamic smem (bf16): 3 x (Ws[128][40] + Xs[32][136]) = 56832 B.
// ---------------------------------------------------------------------------
#define WS_ST 40
#define XS_ST 136
#define WS_STAGE (128 * WS_ST)
#define XS_STAGE (32 * XS_ST)
#define XS_BASE (3 * WS_STAGE)
#define NCHUNK 16
#define PSMEM ((3 * WS_STAGE + 3 * XS_STAGE) * 2)

__global__ __launch_bounds__(256, 2) void proj_tc_kernel(
    const __nv_bfloat16* __restrict__ xin,
    const __nv_bfloat16* __restrict__ Wk, const __nv_bfloat16* __restrict__ Wq,
    const __nv_bfloat16* __restrict__ Wv,
    const float* __restrict__ bkv, const float* __restrict__ bqv, const float* __restrict__ bvv,
    __nv_bfloat16* __restrict__ kqvh)
{
    const int p = blockIdx.z;
    const __nv_bfloat16* __restrict__ W = (p == 0) ? Wk : ((p == 1) ? Wq : Wv);
    const float* __restrict__ Bv = (p == 0) ? bkv : ((p == 1) ? bqv : bvv);
    const int o0 = blockIdx.y << 7;
    const int b0 = blockIdx.x << 1;
    const int t  = threadIdx.x;
    const int w  = t >> 5, lane = t & 31;
    const int wm = w & 1, wn = w >> 1;     // warp tile: 64(m) x 32(n)

    const size_t base0 = (size_t)(b0 >> 6) * ((size_t)C * 4096) + (size_t)(b0 & 63) * 64;
    const size_t base1 = (size_t)((b0 + 1) >> 6) * ((size_t)C * 4096) + (size_t)((b0 + 1) & 63) * 64;

    extern __shared__ __nv_bfloat16 smh[];
    __shared__ float stage[8][16][16];
    uint32_t sbase;
    asm("{ .reg .u64 tmp; cvta.to.shared.u64 tmp, %1; cvt.u32.u64 %0, tmp; }"
        : "=r"(sbase) : "l"(smh));

    wmma::fragment<wmma::accumulator, 16, 16, 16, float> acc[4][2];
    #pragma unroll
    for (int mt = 0; mt < 4; ++mt)
        #pragma unroll
        for (int nt = 0; nt < 2; ++nt)
            wmma::fill_fragment(acc[mt][nt], 0.0f);

    auto load_stage = [&](int s, int kk) {
        uint32_t wbase = sbase + (uint32_t)(s * WS_STAGE) * 2u;
        #pragma unroll
        for (int r2 = 0; r2 < 2; ++r2) {
            int f = r2 * 256 + t;
            int o = f >> 2, c8 = (f & 3) << 3;
            cp16(wbase + (uint32_t)(o * WS_ST + c8) * 2u,
                 &W[(size_t)(o0 + o) * C + kk + c8]);
        }
        uint32_t xbase = sbase + (uint32_t)(XS_BASE + s * XS_STAGE) * 2u;
        #pragma unroll
        for (int r2 = 0; r2 < 2; ++r2) {
            int f = r2 * 256 + t;
            int k = f >> 4, n8 = (f & 15) << 3;
            size_t bb = (n8 < 64) ? base0 : base1;
            cp16(xbase + (uint32_t)(k * XS_ST + n8) * 2u,
                 &xin[bb + (size_t)(kk + k) * 4096 + (n8 & 63)]);
        }
        cp_commit();
    };

    // prologue: stages 0,1 in flight
    load_stage(0, 0);
    load_stage(1, 32);

    for (int i = 0; i < NCHUNK; ++i) {
        const int s = i % 3;
        if (i < NCHUNK - 1) { cp_wait<1>(); } else { cp_wait<0>(); }
        __syncthreads();
        if (i + 2 < NCHUNK) load_stage((i + 2) % 3, (i + 2) * 32);

        const __nv_bfloat16* Wsm = smh + s * WS_STAGE;
        const __nv_bfloat16* Xsm = smh + XS_BASE + s * XS_STAGE;
        #pragma unroll
        for (int ks = 0; ks < 2; ++ks) {
            wmma::fragment<wmma::matrix_a, 16, 16, 16, __nv_bfloat16, wmma::row_major> af[4];
            wmma::fragment<wmma::matrix_b, 16, 16, 16, __nv_bfloat16, wmma::row_major> bf[2];
            #pragma unroll
            for (int mt = 0; mt < 4; ++mt)
                wmma::load_matrix_sync(af[mt], &Wsm[((wm << 6) + (mt << 4)) * WS_ST + (ks << 4)], WS_ST);
            #pragma unroll
            for (int nt = 0; nt < 2; ++nt)
                wmma::load_matrix_sync(bf[nt], &Xsm[(ks << 4) * XS_ST + (wn << 5) + (nt << 4)], XS_ST);
            #pragma unroll
            for (int mt = 0; mt < 4; ++mt)
                #pragma unroll
                for (int nt = 0; nt < 2; ++nt)
                    wmma::mma_sync(acc[mt][nt], af[mt], bf[nt], acc[mt][nt]);
        }
    }
    __syncthreads();

    // Epilogue: fp32 acc (+bias) -> smem staging -> bf16 gmem
    float* st = &stage[w][0][0];
    const int row = lane >> 1, half = lane & 1;
    #pragma unroll
    for (int mt = 0; mt < 4; ++mt) {
        int mrow = o0 + (wm << 6) + (mt << 4);
        float bias = __ldg(&Bv[mrow + row]);
        #pragma unroll
        for (int nt = 0; nt < 2; ++nt) {
            int n0 = (wn << 5) + (nt << 4);
            int bq_idx = b0 + (n0 >> 6);
            int nl0 = n0 & 63;
            wmma::store_matrix_sync(st, acc[mt][nt], 16, wmma::mem_row_major);
            __syncwarp();
            float4 v0 = *(float4*)&st[row * 16 + half * 8];
            float4 v1 = *(float4*)&st[row * 16 + half * 8 + 4];
            v0.x += bias; v0.y += bias; v0.z += bias; v0.w += bias;
            v1.x += bias; v1.y += bias; v1.z += bias; v1.w += bias;
            uint4 u;
            __nv_bfloat162 h0 = __floats2bfloat162_rn(v0.x, v0.y);
            __nv_bfloat162 h1 = __floats2bfloat162_rn(v0.z, v0.w);
            __nv_bfloat162 h2 = __floats2bfloat162_rn(v1.x, v1.y);
            __nv_bfloat162 h3 = __floats2bfloat162_rn(v1.z, v1.w);
            u.x = *(uint32_t*)&h0; u.y = *(uint32_t*)&h1;
            u.z = *(uint32_t*)&h2; u.w = *(uint32_t*)&h3;
            size_t g = ((size_t)(p * NB + bq_idx) * C + mrow + row) * 64 + nl0 + half * 8;
            *(uint4*)&kqvh[g] = u;
            __syncwarp();
        }
    }
}

// ---------------------------------------------------------------------------
// Tensor-core attention: one CTA per (batch, head). kqvh already has bias.
// K/Q/V smem fill is pure cp.async (no register roundtrip).
// Wt (softmax weights) overlays Kh. smem 45056 B -> 5 CTA/SM.
// ---------------------------------------------------------------------------
#define AST 72   // bf16 row stride (elems)
#define SST 68   // fp32 row stride (elems)
#define ASMEM (3 * 64 * AST * 2 + 64 * SST * 4)   // K/Q/V bf16 + S fp32 = 45056

__global__ __launch_bounds__(256) void attn_kernel(
    const __nv_bfloat16* __restrict__ kqvh,
    float* __restrict__ obuf,
    const float* __restrict__ masks,
    int maskT)
{
    const int b = blockIdx.x;
    const int h = blockIdx.y;
    const int t = threadIdx.x;

    extern __shared__ char smraw[];
    __nv_bfloat16* Kh = (__nv_bfloat16*)smraw;          // [64][AST]
    __nv_bfloat16* Qh = Kh + 64 * AST;
    __nv_bfloat16* Vh = Qh + 64 * AST;
    __nv_bfloat16* Wt = Kh;                             // OVERLAY: weights [k][q]
    float* S = (float*)(Vh + 64 * AST);                 // logits [k][q], [64][SST]
    __shared__ float Msm[64];

    const size_t kb = (size_t)b * (C * 64);
    const __nv_bfloat16* __restrict__ Kg = kqvh + kb;
    const uint32_t sb = smem_u32(smraw);

    // cp.async K/Q/V tiles: 3 tensors x 512 16B-chunks = 1536; 6 per thread.
    #pragma unroll
    for (int i = 0; i < 6; ++i) {
        int f = i * 256 + t;                  // 0..1535
        int tz = f >> 9;                      // tensor 0..2
        int e  = f & 511;
        int ch = e >> 3, c8 = (e & 7) << 3;   // 16B chunk within row
        const __nv_bfloat16* src = Kg + (size_t)tz * NBC64
                                 + (size_t)(ch * NH + h) * 64 + c8;
        uint32_t dst = sb + (uint32_t)(tz * 64 * AST + ch * AST + c8) * 2u;
        cp16(dst, src);
    }
    cp_commit();

    const int bs = b >> 6, idx = b & 63;
    if (t < 64) {
        Msm[t] = maskT ? masks[bs * 4096 + t * 64 + idx]
                       : masks[bs * 4096 + idx * 64 + t];
    }
    cp_wait<0>();
    __syncthreads();

    // ---- logits S[k][q] = sum_ch K[ch][k]*Q[ch][q]  (wmma, A=K col_major) ----
    const int w = t >> 5;
    const int mt = w & 3;              // k-tile (also ch-tile in AV)
    const int ntb = (w >> 2) << 1;     // first of 2 q-tiles
    {
        wmma::fragment<wmma::accumulator, 16, 16, 16, float> sacc[2];
        wmma::fill_fragment(sacc[0], 0.0f);
        wmma::fill_fragment(sacc[1], 0.0f);
        #pragma unroll
        for (int kc = 0; kc < 4; ++kc) {
            wmma::fragment<wmma::matrix_a, 16, 16, 16, __nv_bfloat16, wmma::col_major> a;
            wmma::load_matrix_sync(a, Kh + kc * 16 * AST + mt * 16, AST);
            #pragma unroll
            for (int j = 0; j < 2; ++j) {
                wmma::fragment<wmma::matrix_b, 16, 16, 16, __nv_bfloat16, wmma::row_major> bq;
                wmma::load_matrix_sync(bq, Qh + kc * 16 * AST + (ntb + j) * 16, AST);
                wmma::mma_sync(sacc[j], a, bq, sacc[j]);
            }
        }
        #pragma unroll
        for (int j = 0; j < 2; ++j)
            wmma::store_matrix_sync(&S[(mt * 16) * SST + (ntb + j) * 16], sacc[j],
                                    SST, wmma::mem_row_major);
    }
    __syncthreads();   // Kh last read above; Wt(=Kh) written below

    // ---- softmax over k (thread (kg,qg) owns 4x4 of S) ----
    const int kg = t & 15, qg = t >> 4;
    const int k0 = kg << 2, q0l = qg << 2;
    float acc[4][4];
    const float scale = 0.044194173824159216f;  // 1/sqrt(512)
    #pragma unroll
    for (int i = 0; i < 4; ++i) {
        float4 v = *(const float4*)&S[(k0 + i) * SST + q0l];
        float mpen = (1.0f - Msm[k0 + i]) * 1e8f;
        acc[i][0] = v.x * scale - mpen;
        acc[i][1] = v.y * scale - mpen;
        acc[i][2] = v.z * scale - mpen;
        acc[i][3] = v.w * scale - mpen;
    }
    #pragma unroll
    for (int j = 0; j < 4; ++j) {
        float mx = acc[0][j];
        #pragma unroll
        for (int i = 1; i < 4; ++i) mx = fmaxf(mx, acc[i][j]);
        #pragma unroll
        for (int off = 1; off < 16; off <<= 1)
            mx = fmaxf(mx, __shfl_xor_sync(0xffffffffu, mx, off));
        float s = 0.0f;
        float e[4];
        #pragma unroll
        for (int i = 0; i < 4; ++i) {
            e[i] = __expf(acc[i][j] - mx);
            s += e[i];
        }
        #pragma unroll
        for (int off = 1; off < 16; off <<= 1)
            s += __shfl_xor_sync(0xffffffffu, s, off);
        float inv = 1.0f / s;
        #pragma unroll
        for (int i = 0; i < 4; ++i) acc[i][j] = e[i] * inv;
    }
    // write weights (bf16) to Wt[k][q]  (overlays Kh)
    #pragma unroll
    for (int i = 0; i < 4; ++i) {
        __nv_bfloat162 w0 = __floats2bfloat162_rn(acc[i][0], acc[i][1]);
        __nv_bfloat162 w1 = __floats2bfloat162_rn(acc[i][2], acc[i][3]);
        uint2 u;
        u.x = *(uint32_t*)&w0;
        u.y = *(uint32_t*)&w1;
        *(uint2*)&Wt[(k0 + i) * AST + q0l] = u;
    }
    __syncthreads();

    // ---- O[ch][q] = sum_k V[ch][k] * Wt[k][q]  (wmma) -> obuf fp32 ----
    {
        wmma::fragment<wmma::accumulator, 16, 16, 16, float> oacc[2];
        wmma::fill_fragment(oacc[0], 0.0f);
        wmma::fill_fragment(oacc[1], 0.0f);
        #pragma unroll
        for (int kc = 0; kc < 4; ++kc) {
            wmma::fragment<wmma::matrix_a, 16, 16, 16, __nv_bfloat16, wmma::row_major> a;
            wmma::load_matrix_sync(a, Vh + (mt * 16) * AST + kc * 16, AST);
            #pragma unroll
            for (int j = 0; j < 2; ++j) {
                wmma::fragment<wmma::matrix_b, 16, 16, 16, __nv_bfloat16, wmma::row_major> bw;
                wmma::load_matrix_sync(bw, Wt + (kc * 16) * AST + (ntb + j) * 16, AST);
                wmma::mma_sync(oacc[j], a, bw, oacc[j]);
            }
        }
        float* ob = obuf + (size_t)b * (C * 64) + h * 64;
        #pragma unroll
        for (int j = 0; j < 2; ++j)
            wmma::store_matrix_sync(ob + (size_t)(mt * 16) * 512 + (ntb + j) * 16,
                                    oacc[j], 512, wmma::mem_row_major);
    }
}

// ---------------------------------------------------------------------------
// Fused transpose + residual: out[bs][c][j][i] = in[bs][c][i][j] + O[bs*64+i][c][j]
// Also writes a bf16 copy for the next projection.
// ---------------------------------------------------------------------------
__global__ __launch_bounds__(256) void addT_kernel(
    const float* __restrict__ in,
    const float* __restrict__ obuf,
    float* __restrict__ out,
    __nv_bfloat16* __restrict__ outH)
{
    const int bc = blockIdx.x;
    const int bs = bc >> 9, c = bc & 511;
    const int t = threadIdx.x;
    __shared__ float sm[64][65];

    const size_t inb = (size_t)bs * ((size_t)C * 4096) + (size_t)c * 4096;

    #pragma unroll
    for (int p = 0; p < 4; ++p) {
        int r = p * 16 + (t >> 4);
        int j4 = (t & 15) << 2;
        float4 xv = *(const float4*)&in[inb + (size_t)r * 64 + j4];
        float4 ov = *(const float4*)&obuf[((size_t)(bs * 64 + r) * C + c) * 64 + j4];
        sm[r][j4 + 0] = xv.x + ov.x;
        sm[r][j4 + 1] = xv.y + ov.y;
        sm[r][j4 + 2] = xv.z + ov.z;
        sm[r][j4 + 3] = xv.w + ov.w;
    }
    __syncthreads();
    #pragma unroll
    for (int p = 0; p < 4; ++p) {
        int j = p * 16 + (t >> 4);
        int i4 = (t & 15) << 2;
        float4 val = make_float4(sm[i4 + 0][j], sm[i4 + 1][j],
                                 sm[i4 + 2][j], sm[i4 + 3][j]);
        *(float4*)&out[inb + (size_t)j * 64 + i4] = val;
        st_bf4(&outH[inb + (size_t)j * 64 + i4], val);
    }
}

__global__ void copy_masks_kernel(const float* __restrict__ m, float* __restrict__ o)
{
    int i = blockIdx.x * 256 + threadIdx.x;
    if (i < NM) o[i] = m[i];
}

// ---------------------------------------------------------------------------
extern "C" void kernel_launch(void* const* d_in, const int* in_sizes, int n_in,
                              void* d_out, int out_size)
{
    const float* x     = (const float*)d_in[0];
    const float* masks = (const float*)d_in[1];

    const float* W[6];
    const float* B[6];
    if (n_in >= 14 && in_sizes[3] == 3 * C) {
        const int wi[6] = {2, 4, 6, 8, 10, 12};
        const int bi[6] = {3, 5, 7, 9, 11, 13};
        for (int i = 0; i < 6; ++i) {
            W[i] = (const float*)d_in[wi[i]];
            B[i] = (const float*)d_in[bi[i]];
        }
    } else {
        for (int i = 0; i < 6; ++i) {
            W[i] = (const float*)d_in[2 + i];
            B[i] = (const float*)d_in[8 + i];
        }
    }

    float *xA, *xB, *obuf;
    __nv_bfloat16 *xAh, *xBh, *Wh, *kqvh;
    cudaGetSymbolAddress((void**)&xA,   g_xA);
    cudaGetSymbolAddress((void**)&xB,   g_xB);
    cudaGetSymbolAddress((void**)&xAh,  g_xAh);
    cudaGetSymbolAddress((void**)&xBh,  g_xBh);
    cudaGetSymbolAddress((void**)&Wh,   g_Wh);
    cudaGetSymbolAddress((void**)&obuf, g_obuf);
    cudaGetSymbolAddress((void**)&kqvh, g_kqvh);

    cudaFuncSetAttribute(attn_kernel, cudaFuncAttributeMaxDynamicSharedMemorySize, ASMEM);
    cudaFuncSetAttribute(proj_tc_kernel, cudaFuncAttributeMaxDynamicSharedMemorySize, PSMEM);

    // Prepass: bf16 conversion of weights and layer-0 x
    conv_w_kernel<<<(6 * WCC / 4 + 255) / 256, 256>>>(
        W[0], W[1], W[2], W[3], W[4], W[5], Wh);
    conv_x_kernel<<<NX / 1024, 256>>>(x, xAh);

    float* xo = (float*)d_out;
    const float* xin = x;                       // exact fp32 x for residual
    const __nv_bfloat16* xinh = xAh;            // bf16 x for proj
    for (int l = 0; l < 3; ++l) {
        size_t wo = (size_t)l * C * C;
        size_t bo = (size_t)l * C;
        // column attention (layout A in, layout B out)
        proj_tc_kernel<<<dim3(NB / 2, 4, 3), 256, PSMEM>>>(
            xinh, Wh + 0 * WCC + wo, Wh + 1 * WCC + wo, Wh + 2 * WCC + wo,
            B[0] + bo, B[1] + bo, B[2] + bo, kqvh);
        attn_kernel<<<dim3(NB, NH), 256, ASMEM>>>(kqvh, obuf, masks, 0);
        addT_kernel<<<BS * C, 256>>>(xin, obuf, xB, xBh);
        // row attention (layout B in, layout A out)
        proj_tc_kernel<<<dim3(NB / 2, 4, 3), 256, PSMEM>>>(
            xBh, Wh + 3 * WCC + wo, Wh + 4 * WCC + wo, Wh + 5 * WCC + wo,
            B[3] + bo, B[4] + bo, B[5] + bo, kqvh);
        attn_kernel<<<dim3(NB, NH), 256, ASMEM>>>(kqvh, obuf, masks, 1);
        float* xout = (l == 2) ? xo : xA;
        addT_kernel<<<BS * C, 256>>>(xB, obuf, xout, xAh);
        xin = xA;
        xinh = xAh;
    }

    if (out_size >= NX + NM) {
        copy_masks_kernel<<<(NM + 255) / 256, 256>>>(masks, xo + NX);
    }
}